// round 6
// baseline (speedup 1.0000x reference)
#include <cuda_runtime.h>

#define NOBJ   4096
#define DIM    1024
#define DIM2   2048
#define NREL   8
#define NPAIR  65536

// Scratch (device globals — no allocation allowed)
__device__ float g_Mpart[16 * NREL * DIM2]; // split-K partials, 1 MB
__device__ float g_M[NREL * DIM2];          // fused weight M = W2 @ W1, 64 KB
__device__ float g_c[NREL];                 // fused bias c = W2@b1 + b2
__device__ float g_U[NOBJ * 16];            // per-object projections, 256 KB
                                            //   [o][0:8]  = f·M[:, :1024]ᵀ
                                            //   [o][8:16] = f·M[:, 1024:]ᵀ + c

// Packed fp32x2 FMA: d = a*b + d elementwise on (lo,hi) pairs.
__device__ __forceinline__ void ffma2(unsigned long long& acc,
                                      unsigned long long a,
                                      unsigned long long b) {
    asm("fma.rn.f32x2 %0, %1, %2, %0;" : "+l"(acc) : "l"(a), "l"(b));
}

__device__ __forceinline__ float4 f4fma(float s, float4 v, float4 a) {
    a.x += s * v.x; a.y += s * v.y; a.z += s * v.z; a.w += s * v.w;
    return a;
}

// ---------------------------------------------------------------------------
// Stage A: Mpart[ic][r][j] = sum_{i in ichunk} W2[r][i] * W1[i][j]
// Grid 256 = (16 j-chunks x 16 i-chunks), 256 threads.
// Block: jchunk = 128 j (32 float4), ichunk = 64 i (8 warps x 8 i).
// Thread: 8 independent float4 W1 loads (MLP=8, 512 B contiguous per warp-row).
// ---------------------------------------------------------------------------
__global__ void __launch_bounds__(256) m_partial_kernel(const float* __restrict__ W1,
                                                        const float* __restrict__ W2) {
    __shared__ float  sW2[NREL][64];     // 2 KB
    __shared__ float4 sAcc[8][256];      // 32 KB [iw][r*32+jq]
    const int tx = threadIdx.x;
    const int jc = blockIdx.x & 15;
    const int ic = blockIdx.x >> 4;
    const int jbase = jc * 128;
    const int ibase = ic * 64;

    if (tx < 128) {     // stage W2 chunk: 8 r x 64 i
        const int r = tx >> 4, q = tx & 15;
        *(float4*)&sW2[r][q * 4] = __ldg((const float4*)&W2[r * DIM + ibase + q * 4]);
    }
    __syncthreads();

    const int jq = tx & 31;          // float4 column within j-chunk
    const int iw = tx >> 5;          // warp id -> 8 i's

    float4 w1v[8];
#pragma unroll
    for (int u = 0; u < 8; u++) {    // all 8 loads independent
        const int i = ibase + iw * 8 + u;
        w1v[u] = __ldg((const float4*)(W1 + i * DIM2 + jbase + jq * 4));
    }

    float4 acc[NREL];
#pragma unroll
    for (int r = 0; r < NREL; r++) acc[r] = make_float4(0.f, 0.f, 0.f, 0.f);
#pragma unroll
    for (int u = 0; u < 8; u++) {
        const int il = iw * 8 + u;
#pragma unroll
        for (int r = 0; r < NREL; r++) acc[r] = f4fma(sW2[r][il], w1v[u], acc[r]);
    }
#pragma unroll
    for (int r = 0; r < NREL; r++) sAcc[iw][r * 32 + jq] = acc[r];
    __syncthreads();

    // 256 threads: r = tx>>5, jq2 = tx&31 -> reduce 8 warps in fixed order
    const int r = tx >> 5, jq2 = tx & 31;
    float4 s = sAcc[0][r * 32 + jq2];
#pragma unroll
    for (int w = 1; w < 8; w++) {
        float4 p = sAcc[w][r * 32 + jq2];
        s.x += p.x; s.y += p.y; s.z += p.z; s.w += p.w;
    }
    ((float4*)g_Mpart)[ic * 4096 + r * 512 + jc * 32 + jq2] = s;
}

// ---------------------------------------------------------------------------
// Stage B: M = sum over 16 i-chunks (fixed order), float4, MLP=16.
// Block 0 additionally computes c[r] = W2[r]·b1 + b2[r].
// Grid 16 x 256.
// ---------------------------------------------------------------------------
__global__ void __launch_bounds__(256) m_reduce_kernel(const float* __restrict__ W2,
                                                       const float* __restrict__ b1,
                                                       const float* __restrict__ b2) {
    const int g4 = blockIdx.x * 256 + threadIdx.x;    // 0..4095
    const float4* __restrict__ P4 = (const float4*)g_Mpart;
    float4 s = P4[g4];
#pragma unroll
    for (int ic = 1; ic < 16; ic++) {
        float4 p = P4[ic * 4096 + g4];
        s.x += p.x; s.y += p.y; s.z += p.z; s.w += p.w;
    }
    ((float4*)g_M)[g4] = s;

    if (blockIdx.x == 0) {
        const int w = threadIdx.x >> 5, lane = threadIdx.x & 31;
        float t = 0.f;
        for (int i = lane; i < DIM; i += 32) t += b1[i] * W2[w * DIM + i];
#pragma unroll
        for (int off = 16; off; off >>= 1)
            t += __shfl_xor_sync(0xffffffffu, t, off);
        if (lane == 0) g_c[w] = t + b2[w];
    }
}

// ---------------------------------------------------------------------------
// U table: U[o][j] = feats[o] · Mrow_j   (+ c[j] folded into the object half)
// Warp w -> pair = w>>1 (4 objects), half = w&1 (8 j-columns).
// Packed f32x2 FMAs, butterfly-fold reduction. Grid 256 x 256 (2048 warps).
// ---------------------------------------------------------------------------
__global__ void __launch_bounds__(256) u_kernel(const float* __restrict__ feats) {
    const int gw   = (blockIdx.x * 256 + threadIdx.x) >> 5;  // 0..2047
    const int lane = threadIdx.x & 31;
    const int pair = gw >> 1;
    const int half = gw & 1;           // 0: sub cols, 1: obj cols
    const int obase = pair * 4;

    const longlong2* __restrict__ F2 = (const longlong2*)feats;  // 256 per row
    const longlong2* __restrict__ M2 = (const longlong2*)g_M;    // row j at j*512
    const int jbase = half * 256;      // +1024 floats for obj half

    unsigned long long acc[4][8];
#pragma unroll
    for (int k = 0; k < 4; k++)
#pragma unroll
        for (int j = 0; j < 8; j++) acc[k][j] = 0ull;

#pragma unroll 1
    for (int t = 0; t < 8; t++) {      // 8 x 32 lanes x 4 floats = 1024 d
        const int idx = t * 32 + lane;
        unsigned long long fa[4], fb[4];
#pragma unroll
        for (int k = 0; k < 4; k++) {
            longlong2 fv = __ldg(F2 + (obase + k) * 256 + idx);
            fa[k] = (unsigned long long)fv.x;
            fb[k] = (unsigned long long)fv.y;
        }
#pragma unroll
        for (int j = 0; j < 8; j++) {
            longlong2 mv = __ldg(M2 + j * 512 + jbase + idx);
            const unsigned long long ma = (unsigned long long)mv.x;
            const unsigned long long mb = (unsigned long long)mv.y;
#pragma unroll
            for (int k = 0; k < 4; k++) {
                ffma2(acc[k][j], fa[k], ma);
                ffma2(acc[k][j], fb[k], mb);
            }
        }
    }

    // Collapse packed halves -> 32 scalar partials per lane (vi = k*8+j).
    float v[32];
#pragma unroll
    for (int k = 0; k < 4; k++)
#pragma unroll
        for (int j = 0; j < 8; j++) {
            float2 p = *(float2*)&acc[k][j];
            v[k * 8 + j] = p.x + p.y;
        }

    // Butterfly fold: 5 stages, 31 shfl. Lane L ends with the full sum of
    // original index bitrev5(L) in v[0].
    int nv = 32;
#pragma unroll
    for (int d = 1; d < 32; d <<= 1) {
        nv >>= 1;
        const bool up = (lane & d) != 0;
#pragma unroll
        for (int i = 0; i < 16; i++) {
            if (i < nv) {
                float send = up ? v[i] : v[i + nv];
                float recv = __shfl_xor_sync(0xffffffffu, send, d);
                v[i] = (up ? v[i + nv] : v[i]) + recv;
            }
        }
    }

    const int vi = __brev(lane) >> 27;   // bitrev5
    const int k = vi >> 3;
    const int j = vi & 7;
    const float bias = half ? g_c[j] : 0.f;   // fold c into object half
    g_U[(obase + k) * 16 + half * 8 + j] = v[0] + bias;
}

// ---------------------------------------------------------------------------
// out[p][r] = U[s_p][r] + U[o_p][8+r]   (c already folded into U's obj half)
// 4 pairs per thread: batched pair loads, then 16 independent U loads (MLP).
// Grid 64 x 256.
// ---------------------------------------------------------------------------
__global__ void __launch_bounds__(256) gather_kernel(const int* __restrict__ pairs,
                                                     float* __restrict__ out) {
    const int base = (blockIdx.x * 256 + threadIdx.x) * 4;   // first pair idx
    const int4* __restrict__ P4 = (const int4*)pairs;        // 2 pairs / int4
    int4 pa = __ldg(&P4[(base >> 1) + 0]);
    int4 pb = __ldg(&P4[(base >> 1) + 1]);
    const int s[4] = {pa.x, pa.z, pb.x, pb.z};
    const int o[4] = {pa.y, pa.w, pb.y, pb.w};

    const float4* __restrict__ U4 = (const float4*)g_U;
    float4 a0[4], a1[4], b0[4], b1[4];
#pragma unroll
    for (int k = 0; k < 4; k++) {       // all 16 loads independent
        a0[k] = __ldg(&U4[s[k] * 4 + 0]);
        a1[k] = __ldg(&U4[s[k] * 4 + 1]);
        b0[k] = __ldg(&U4[o[k] * 4 + 2]);
        b1[k] = __ldg(&U4[o[k] * 4 + 3]);
    }
    float4* __restrict__ O4 = (float4*)out;
#pragma unroll
    for (int k = 0; k < 4; k++) {
        float4 r0, r1;
        r0.x = a0[k].x + b0[k].x;  r0.y = a0[k].y + b0[k].y;
        r0.z = a0[k].z + b0[k].z;  r0.w = a0[k].w + b0[k].w;
        r1.x = a1[k].x + b1[k].x;  r1.y = a1[k].y + b1[k].y;
        r1.z = a1[k].z + b1[k].z;  r1.w = a1[k].w + b1[k].w;
        O4[(base + k) * 2 + 0] = r0;
        O4[(base + k) * 2 + 1] = r1;
    }
}

extern "C" void kernel_launch(void* const* d_in, const int* in_sizes, int n_in,
                              void* d_out, int out_size) {
    const float* feats = (const float*)d_in[0];   // (4096, 1024) f32
    const int*   pairs = (const int*)d_in[1];     // (65536, 2) i32
    const float* W1    = (const float*)d_in[2];   // (1024, 2048) f32
    const float* b1    = (const float*)d_in[3];   // (1024,) f32
    const float* W2    = (const float*)d_in[4];   // (8, 1024) f32
    const float* b2    = (const float*)d_in[5];   // (8,) f32
    float*       out   = (float*)d_out;           // (65536, 8) f32

    m_partial_kernel<<<256, 256>>>(W1, W2);
    m_reduce_kernel<<<16, 256>>>(W2, b1, b2);
    u_kernel<<<256, 256>>>(feats);
    gather_kernel<<<64, 256>>>(pairs, out);
}

// round 7
// speedup vs baseline: 1.0015x; 1.0015x over previous
#include <cuda_runtime.h>

#define NOBJ   4096
#define DIM    1024
#define DIM2   2048
#define NREL   8
#define NPAIR  65536

// Scratch (device globals — no allocation allowed)
__device__ float g_Mpart[16 * NREL * DIM2]; // split-K partials, 1 MB
__device__ float g_M[NREL * DIM2];          // fused weight M = W2 @ W1, 64 KB
__device__ float g_c[NREL];                 // fused bias c = W2@b1 + b2
__device__ float g_U[NOBJ * 16];            // per-object projections, 256 KB
                                            //   [o][0:8]  = f·M[:, :1024]ᵀ
                                            //   [o][8:16] = f·M[:, 1024:]ᵀ + c

// Packed fp32x2 FMA: d = a*b + d elementwise on (lo,hi) pairs.
__device__ __forceinline__ void ffma2(unsigned long long& acc,
                                      unsigned long long a,
                                      unsigned long long b) {
    asm("fma.rn.f32x2 %0, %1, %2, %0;" : "+l"(acc) : "l"(a), "l"(b));
}

__device__ __forceinline__ float4 f4fma(float s, float4 v, float4 a) {
    a.x += s * v.x; a.y += s * v.y; a.z += s * v.z; a.w += s * v.w;
    return a;
}

// ---------------------------------------------------------------------------
// Stage A: Mpart[ic][r][j] = sum_{i in ichunk} W2[r][i] * W1[i][j]
// Grid 256 = (16 j-chunks x 16 i-chunks), 256 threads.
// Block: jchunk = 128 j (32 float4), ichunk = 64 i (8 warps x 8 i).
// Thread: 8 independent float4 W1 loads (MLP=8, 512 B contiguous per warp-row).
// ---------------------------------------------------------------------------
__global__ void __launch_bounds__(256) m_partial_kernel(const float* __restrict__ W1,
                                                        const float* __restrict__ W2) {
    __shared__ float  sW2[NREL][64];     // 2 KB
    __shared__ float4 sAcc[8][256];      // 32 KB [iw][r*32+jq]
    const int tx = threadIdx.x;
    const int jc = blockIdx.x & 15;
    const int ic = blockIdx.x >> 4;
    const int jbase = jc * 128;
    const int ibase = ic * 64;

    if (tx < 128) {     // stage W2 chunk: 8 r x 64 i
        const int r = tx >> 4, q = tx & 15;
        *(float4*)&sW2[r][q * 4] = __ldg((const float4*)&W2[r * DIM + ibase + q * 4]);
    }
    __syncthreads();

    const int jq = tx & 31;          // float4 column within j-chunk
    const int iw = tx >> 5;          // warp id -> 8 i's

    float4 w1v[8];
#pragma unroll
    for (int u = 0; u < 8; u++) {    // all 8 loads independent
        const int i = ibase + iw * 8 + u;
        w1v[u] = __ldg((const float4*)(W1 + i * DIM2 + jbase + jq * 4));
    }

    float4 acc[NREL];
#pragma unroll
    for (int r = 0; r < NREL; r++) acc[r] = make_float4(0.f, 0.f, 0.f, 0.f);
#pragma unroll
    for (int u = 0; u < 8; u++) {
        const int il = iw * 8 + u;
#pragma unroll
        for (int r = 0; r < NREL; r++) acc[r] = f4fma(sW2[r][il], w1v[u], acc[r]);
    }
#pragma unroll
    for (int r = 0; r < NREL; r++) sAcc[iw][r * 32 + jq] = acc[r];
    __syncthreads();

    // 256 threads: r = tx>>5, jq2 = tx&31 -> reduce 8 warps in fixed order
    const int r = tx >> 5, jq2 = tx & 31;
    float4 s = sAcc[0][r * 32 + jq2];
#pragma unroll
    for (int w = 1; w < 8; w++) {
        float4 p = sAcc[w][r * 32 + jq2];
        s.x += p.x; s.y += p.y; s.z += p.z; s.w += p.w;
    }
    ((float4*)g_Mpart)[ic * 4096 + r * 512 + jc * 32 + jq2] = s;
}

// ---------------------------------------------------------------------------
// Stage B: M = sum over 16 i-chunks (fixed order), float4, MLP=16.
// Block 0 additionally computes c[r] = W2[r]·b1 + b2[r].
// Grid 16 x 256.
// ---------------------------------------------------------------------------
__global__ void __launch_bounds__(256) m_reduce_kernel(const float* __restrict__ W2,
                                                       const float* __restrict__ b1,
                                                       const float* __restrict__ b2) {
    const int g4 = blockIdx.x * 256 + threadIdx.x;    // 0..4095
    const float4* __restrict__ P4 = (const float4*)g_Mpart;
    float4 s = P4[g4];
#pragma unroll
    for (int ic = 1; ic < 16; ic++) {
        float4 p = P4[ic * 4096 + g4];
        s.x += p.x; s.y += p.y; s.z += p.z; s.w += p.w;
    }
    ((float4*)g_M)[g4] = s;

    if (blockIdx.x == 0) {
        const int w = threadIdx.x >> 5, lane = threadIdx.x & 31;
        float t = 0.f;
        for (int i = lane; i < DIM; i += 32) t += b1[i] * W2[w * DIM + i];
#pragma unroll
        for (int off = 16; off; off >>= 1)
            t += __shfl_xor_sync(0xffffffffu, t, off);
        if (lane == 0) g_c[w] = t + b2[w];
    }
}

// ---------------------------------------------------------------------------
// U table: U[o][j] = feats[o] · Mrow_j   (+ c[j] folded into the object half)
// Warp w -> pair = w>>1 (4 objects), half = w&1 (8 j-columns).
// Packed f32x2 FMAs, butterfly-fold reduction. Grid 256 x 256 (2048 warps).
// ---------------------------------------------------------------------------
__global__ void __launch_bounds__(256) u_kernel(const float* __restrict__ feats) {
    const int gw   = (blockIdx.x * 256 + threadIdx.x) >> 5;  // 0..2047
    const int lane = threadIdx.x & 31;
    const int pair = gw >> 1;
    const int half = gw & 1;           // 0: sub cols, 1: obj cols
    const int obase = pair * 4;

    const longlong2* __restrict__ F2 = (const longlong2*)feats;  // 256 per row
    const longlong2* __restrict__ M2 = (const longlong2*)g_M;    // row j at j*512
    const int jbase = half * 256;      // +1024 floats for obj half

    unsigned long long acc[4][8];
#pragma unroll
    for (int k = 0; k < 4; k++)
#pragma unroll
        for (int j = 0; j < 8; j++) acc[k][j] = 0ull;

#pragma unroll 1
    for (int t = 0; t < 8; t++) {      // 8 x 32 lanes x 4 floats = 1024 d
        const int idx = t * 32 + lane;
        unsigned long long fa[4], fb[4];
#pragma unroll
        for (int k = 0; k < 4; k++) {
            longlong2 fv = __ldg(F2 + (obase + k) * 256 + idx);
            fa[k] = (unsigned long long)fv.x;
            fb[k] = (unsigned long long)fv.y;
        }
#pragma unroll
        for (int j = 0; j < 8; j++) {
            longlong2 mv = __ldg(M2 + j * 512 + jbase + idx);
            const unsigned long long ma = (unsigned long long)mv.x;
            const unsigned long long mb = (unsigned long long)mv.y;
#pragma unroll
            for (int k = 0; k < 4; k++) {
                ffma2(acc[k][j], fa[k], ma);
                ffma2(acc[k][j], fb[k], mb);
            }
        }
    }

    // Collapse packed halves -> 32 scalar partials per lane (vi = k*8+j).
    float v[32];
#pragma unroll
    for (int k = 0; k < 4; k++)
#pragma unroll
        for (int j = 0; j < 8; j++) {
            float2 p = *(float2*)&acc[k][j];
            v[k * 8 + j] = p.x + p.y;
        }

    // Butterfly fold: 5 stages, 31 shfl. Lane L ends with the full sum of
    // original index bitrev5(L) in v[0].
    int nv = 32;
#pragma unroll
    for (int d = 1; d < 32; d <<= 1) {
        nv >>= 1;
        const bool up = (lane & d) != 0;
#pragma unroll
        for (int i = 0; i < 16; i++) {
            if (i < nv) {
                float send = up ? v[i] : v[i + nv];
                float recv = __shfl_xor_sync(0xffffffffu, send, d);
                v[i] = (up ? v[i + nv] : v[i]) + recv;
            }
        }
    }

    const int vi = __brev(lane) >> 27;   // bitrev5
    const int k = vi >> 3;
    const int j = vi & 7;
    const float bias = half ? g_c[j] : 0.f;   // fold c into object half
    g_U[(obase + k) * 16 + half * 8 + j] = v[0] + bias;
}

// ---------------------------------------------------------------------------
// out[p][r] = U[s_p][r] + U[o_p][8+r]   (c already folded into U's obj half)
// 2 pairs per thread, 256 blocks x 128 threads (32768 threads):
// 1 int4 pair load -> 8 independent float4 U loads (MLP=8) -> 4 stores.
// ---------------------------------------------------------------------------
__global__ void __launch_bounds__(128) gather_kernel(const int* __restrict__ pairs,
                                                     float* __restrict__ out) {
    const int t = blockIdx.x * 128 + threadIdx.x;    // 0..32767
    int4 p = __ldg(&((const int4*)pairs)[t]);        // pairs 2t, 2t+1
    const int s0 = p.x, o0 = p.y, s1 = p.z, o1 = p.w;

    const float4* __restrict__ U4 = (const float4*)g_U;
    float4 a00 = __ldg(&U4[s0 * 4 + 0]);
    float4 a01 = __ldg(&U4[s0 * 4 + 1]);
    float4 b00 = __ldg(&U4[o0 * 4 + 2]);
    float4 b01 = __ldg(&U4[o0 * 4 + 3]);
    float4 a10 = __ldg(&U4[s1 * 4 + 0]);
    float4 a11 = __ldg(&U4[s1 * 4 + 1]);
    float4 b10 = __ldg(&U4[o1 * 4 + 2]);
    float4 b11 = __ldg(&U4[o1 * 4 + 3]);

    float4 r0, r1, r2, r3;
    r0.x = a00.x + b00.x;  r0.y = a00.y + b00.y;
    r0.z = a00.z + b00.z;  r0.w = a00.w + b00.w;
    r1.x = a01.x + b01.x;  r1.y = a01.y + b01.y;
    r1.z = a01.z + b01.z;  r1.w = a01.w + b01.w;
    r2.x = a10.x + b10.x;  r2.y = a10.y + b10.y;
    r2.z = a10.z + b10.z;  r2.w = a10.w + b10.w;
    r3.x = a11.x + b11.x;  r3.y = a11.y + b11.y;
    r3.z = a11.z + b11.z;  r3.w = a11.w + b11.w;

    float4* __restrict__ O4 = (float4*)out;
    O4[t * 4 + 0] = r0;
    O4[t * 4 + 1] = r1;
    O4[t * 4 + 2] = r2;
    O4[t * 4 + 3] = r3;
}

extern "C" void kernel_launch(void* const* d_in, const int* in_sizes, int n_in,
                              void* d_out, int out_size) {
    const float* feats = (const float*)d_in[0];   // (4096, 1024) f32
    const int*   pairs = (const int*)d_in[1];     // (65536, 2) i32
    const float* W1    = (const float*)d_in[2];   // (1024, 2048) f32
    const float* b1    = (const float*)d_in[3];   // (1024,) f32
    const float* W2    = (const float*)d_in[4];   // (8, 1024) f32
    const float* b2    = (const float*)d_in[5];   // (8,) f32
    float*       out   = (float*)d_out;           // (65536, 8) f32

    m_partial_kernel<<<256, 256>>>(W1, W2);
    m_reduce_kernel<<<16, 256>>>(W2, b1, b2);
    u_kernel<<<256, 256>>>(feats);
    gather_kernel<<<256, 128>>>(pairs, out);
}